// round 3
// baseline (speedup 1.0000x reference)
#include <cuda_runtime.h>

#define A_    96
#define DET0_ 256
#define T_    256
#define NZ_   32
#define NY_   256
#define NX_   256
#define DTH   0.0327249234748936795f   // pi/96
#define LAMB_ 0.01f
#define ROW_  258                      // padded row length (cells)
#define RS_   (ROW_ * 8)               // float4s per padded row (2064)

// Zero-padded scratch. Pads (index 0 and 257) are NEVER written -> stay zero
// from static init, so OOB bilinear taps read 0 and need no weight masks.
__device__ float g_vol_t[ROW_ * ROW_ * NZ_];   // [(y+1)][(x+1)][z], z fastest
__device__ float g_res_t[A_ * ROW_ * NZ_];     // [a][(u+1)][z], z fastest

__device__ __forceinline__ void fma4(float4& a, float w, const float4 v) {
    a.x = fmaf(w, v.x, a.x);
    a.y = fmaf(w, v.y, a.y);
    a.z = fmaf(w, v.z, a.z);
    a.w = fmaf(w, v.w, a.w);
}

// ---------------------------------------------------------------------------
// Kernel 1: transpose x (z,y,x) -> padded vol_t (y+1, x+1, z).
// 256 threads: read float4 along x (coalesced), write float4 along z.
// ---------------------------------------------------------------------------
__global__ __launch_bounds__(256) void transpose_kernel(const float* __restrict__ x) {
    __shared__ float tile[32][33];   // [z][x]
    const int xb = blockIdx.x * 32;
    const int y  = blockIdx.y;
    {
        const int z  = threadIdx.x >> 3;
        const int xq = threadIdx.x & 7;
        float4 v = reinterpret_cast<const float4*>(x + z * (NY_ * NX_) + y * NX_ + xb)[xq];
        tile[z][4 * xq + 0] = v.x;
        tile[z][4 * xq + 1] = v.y;
        tile[z][4 * xq + 2] = v.z;
        tile[z][4 * xq + 3] = v.w;
    }
    __syncthreads();
    {
        const int tz = threadIdx.x & 7;
        const int xl = threadIdx.x >> 3;
        float4 w = make_float4(tile[4 * tz + 0][xl], tile[4 * tz + 1][xl],
                               tile[4 * tz + 2][xl], tile[4 * tz + 3][xl]);
        reinterpret_cast<float4*>(g_vol_t)[((y + 1) * ROW_ + (xb + xl + 1)) * 8 + tz] = w;
    }
}

// ---------------------------------------------------------------------------
// Kernel 2: forward project + residual, register-cached bilinear taps.
// Block = (16-u tile, angle), 128 threads. zo = tid&7 (float4 of z),
// ul = tid>>3. DIR=+1 for c>=0 (t ascending: dx,dy in {0,1}),
// DIR=-1 for c<0 (t descending: dx in {0,1}, dy in {0,-1}).
// ---------------------------------------------------------------------------
template <int DIR>
__global__ __launch_bounds__(128) void fwd_kernel(const float* __restrict__ p, int a_base) {
    const float4* __restrict__ vol4 = reinterpret_cast<const float4*>(g_vol_t);

    const int tid = threadIdx.x;
    const int zo  = tid & 7;
    const int ul  = tid >> 3;
    const int a   = a_base + blockIdx.y;
    const int u   = blockIdx.x * 16 + ul;

    float s, c;
    sincosf((float)a * DTH, &s, &c);

    const float uc = (float)u - 127.5f;
    const float bx = fmaf(uc, -s, 127.5f);
    const float by = fmaf(uc,  c, 127.5f);

    float4 accA = make_float4(0.f, 0.f, 0.f, 0.f);
    float4 accB = make_float4(0.f, 0.f, 0.f, 0.f);

    float4 v00, v01, v10, v11;
    v00 = v01 = v10 = v11 = make_float4(0.f, 0.f, 0.f, 0.f);
    int  cx = -100000, cy = -100000;
    bool valid = false;

    for (int k = 0; k < T_; ++k) {
        const int t = (DIR > 0) ? k : (T_ - 1 - k);
        const float tf = (float)t - 127.5f;
        const float ix = fmaf(tf, c, bx);
        const float iy = fmaf(tf, s, by);

        const int x0 = __float2int_rd(ix);
        const int y0 = __float2int_rd(iy);
        if ((unsigned)(x0 + 1) > 256u || (unsigned)(y0 + 1) > 256u) { valid = false; continue; }

        const float fx = ix - (float)x0;
        const float fy = iy - (float)y0;

        const int base = (y0 + 1) * RS_ + (x0 + 1) * 8 + zo;

        const int dxi = x0 - cx;
        const int dyi = y0 - cy;
        bool full, xp, ys;
        if (DIR > 0) {
            full = (!valid) | ((unsigned)dxi > 1u) | ((unsigned)dyi > 1u);
            xp = (dxi == 1);
            ys = (dyi == 1);
        } else {
            full = (!valid) | ((unsigned)dxi > 1u) | ((unsigned)(dyi + 1) > 1u);
            xp = (dxi == 1);
            ys = (dyi == -1);
        }

        if (DIR > 0) {
            // vNew[j][i] = vOld[j+dy][i+dx], dx,dy in {0,1}
            const float4 t1 = ys ? v11 : v01;
            const float4 t2 = ys ? v10 : v00;
            v00 = xp ? t1 : t2;
            v01 = t1;                       // valid iff !xp (else loaded)
            v10 = xp ? v11 : v10;           // valid iff !ys (else loaded)
            // v11 stays (valid iff !xp && !ys, else loaded)
            if (full)            v00 = vol4[base];
            if (xp | full)       v01 = vol4[base + 8];
            if (ys | full)       v10 = vol4[base + RS_];
            if (xp | ys | full)  v11 = vol4[base + RS_ + 8];
        } else {
            // dx in {0,1}, dy in {0,-1} (ys means dy==-1)
            const float4 t1 = xp ? v01 : v00;
            const float4 t2 = xp ? v11 : v10;
            v10 = ys ? t1 : t2;
            const float4 s11 = ys ? v01 : v11;   // valid iff !xp
            v00 = t1;                            // valid iff !ys
            v11 = s11;
            // v01 stays (valid iff !xp && !ys)
            if (ys | full)       v00 = vol4[base];
            if (ys | xp | full)  v01 = vol4[base + 8];
            if (full)            v10 = vol4[base + RS_];
            if (xp | full)       v11 = vol4[base + RS_ + 8];
        }

        valid = true; cx = x0; cy = y0;

        const float wx1 = fx, wx0 = 1.0f - fx;
        const float wy1 = fy, wy0 = 1.0f - fy;
        fma4(accA, wy0 * wx0, v00);
        fma4(accB, wy0 * wx1, v01);
        fma4(accA, wy1 * wx0, v10);
        fma4(accB, wy1 * wx1, v11);
    }

    const float accv[4] = {accA.x + accB.x, accA.y + accB.y,
                           accA.z + accB.z, accA.w + accB.w};
    float r[4];
    #pragma unroll
    for (int e = 0; e < 4; ++e) {
        const int z = 4 * zo + e;
        const int m = ((z & 7) << 2) | (z >> 3);
        const float pv = p[(a * 4 + (m >> 3)) * (8 * 256) + (m & 7) * 256 + u];
        r[e] = accv[e] - pv;
    }
    reinterpret_cast<float4*>(g_res_t)[(a * ROW_ + u + 1) * 8 + zo] =
        make_float4(r[0], r[1], r[2], r[3]);
}

// ---------------------------------------------------------------------------
// Kernel 3: back project from padded res (no weight masks needed).
// ---------------------------------------------------------------------------
__global__ __launch_bounds__(256) void bwd_kernel(float* __restrict__ out) {
    __shared__ float2 ang[A_];
    const int tid = threadIdx.x;
    if (tid < A_) {
        float s, c;
        sincosf((float)tid * DTH, &s, &c);
        ang[tid] = make_float2(s, c);
    }
    __syncthreads();

    const int zo   = tid & 7;
    const int slot = tid >> 3;
    const int sx   = slot & 7;
    const int sy   = slot >> 3;
    const int x = blockIdx.x * 8 + sx;
    const int y = blockIdx.y * 4 + sy;

    const float Xc = (float)x - 127.5f;
    const float Yc = (float)y - 127.5f;

    const float4* __restrict__ res4 = reinterpret_cast<const float4*>(g_res_t);

    float4 accA = make_float4(0.f, 0.f, 0.f, 0.f);
    float4 accB = make_float4(0.f, 0.f, 0.f, 0.f);

    #pragma unroll 4
    for (int a = 0; a < A_; ++a) {
        const float s = ang[a].x;
        const float c = ang[a].y;
        const float ub = fmaf(Yc, c, fmaf(Xc, -s, 127.5f));
        const int u0 = __float2int_rd(ub);
        if ((unsigned)(u0 + 1) > 256u) continue;

        const float fu = ub - (float)u0;
        const int b0 = (a * ROW_ + u0 + 1) * 8 + zo;
        fma4(accA, 1.0f - fu, res4[b0]);
        fma4(accB, fu,        res4[b0 + 8]);
    }

    const float L = -LAMB_;
    const int base = y * NX_ + x;
    out[(4 * zo + 0) * (NY_ * NX_) + base] = L * (accA.x + accB.x);
    out[(4 * zo + 1) * (NY_ * NX_) + base] = L * (accA.y + accB.y);
    out[(4 * zo + 2) * (NY_ * NX_) + base] = L * (accA.z + accB.z);
    out[(4 * zo + 3) * (NY_ * NX_) + base] = L * (accA.w + accB.w);
}

// ---------------------------------------------------------------------------
extern "C" void kernel_launch(void* const* d_in, const int* in_sizes, int n_in,
                              void* d_out, int out_size) {
    const float* x = (const float*)d_in[0];
    const float* p = (const float*)d_in[1];
    if (n_in >= 2 && in_sizes[0] == 786432) {   // defensive swap by size
        const float* tmp = x; x = p; p = tmp;
    }
    float* out = (float*)d_out;

    transpose_kernel<<<dim3(NX_ / 32, NY_), 256>>>(x);
    // angles 0..47: c > 0 (t ascending); angles 48..95: c <= 0 (t descending).
    // Robust full-reload guard keeps borderline a=48 correct either way.
    fwd_kernel<+1><<<dim3(DET0_ / 16, 48), 128>>>(p, 0);
    fwd_kernel<-1><<<dim3(DET0_ / 16, 48), 128>>>(p, 48);
    bwd_kernel<<<dim3(NX_ / 8, NY_ / 4), 256>>>(out);
}

// round 5
// speedup vs baseline: 1.5508x; 1.5508x over previous
#include <cuda_runtime.h>
#include <cuda_fp16.h>

#define A_    96
#define DET0_ 256
#define T_    256
#define NZ_   32
#define NY_   256
#define NX_   256
#define DTH   0.0327249234748936795f   // pi/96
#define LAMB_ 0.01f

#define VROW_  130                      // pair-cells per padded vol row
#define VH_    258                      // padded rows (y)
#define COPYH  (VH_ * VROW_ * 64)       // halves per vol copy
#define RROW_  258                      // padded res row (u cells)

// fp16 scratch (zero static init; pad cells NEVER written -> stay zero forever,
// so OOB bilinear taps read 0 with no masks).
// g_vol_h: two copies of x-pair-interleaved volume.
//   copy0 cell pe: (x=2pe-1, x=2pe)   [px even at left]
//   copy1 cell pb: (x=2pb,   x=2pb+1) [px odd  at left]
//   cell = [z 0..31][left,right] halves = 128 B line.
__device__ __half g_vol_h[2 * COPYH];
__device__ __half g_res_h[A_ * RROW_ * 32];    // [a][(u+1)][z], 64 B cells

__device__ __forceinline__ float2 h2f(unsigned v) {
    __half2 h = *reinterpret_cast<const __half2*>(&v);
    return __half22float2(h);
}

// ---------------------------------------------------------------------------
// Kernel 1: transpose+pack x (z,y,x fp32) -> dual-copy fp16 pair cells.
// Block: one y row x 32-x tile, 256 threads. smem tile has 34 cols
// (col 0 = x-1 for cross-tile pairs).
// ---------------------------------------------------------------------------
__global__ __launch_bounds__(256) void pack_kernel(const float* __restrict__ x) {
    __shared__ float tile[32][34];   // [z][col], col j <-> x = xb-1+j
    const int xb = blockIdx.x * 32;
    const int y  = blockIdx.y;
    {
        const int z  = threadIdx.x >> 3;
        const int xq = threadIdx.x & 7;
        float4 v = reinterpret_cast<const float4*>(x + z * (NY_ * NX_) + y * NX_ + xb)[xq];
        tile[z][1 + 4 * xq + 0] = v.x;
        tile[z][1 + 4 * xq + 1] = v.y;
        tile[z][1 + 4 * xq + 2] = v.z;
        tile[z][1 + 4 * xq + 3] = v.w;
    }
    if (threadIdx.x < 32) {
        tile[threadIdx.x][0] = (xb > 0)
            ? x[threadIdx.x * (NY_ * NX_) + y * NX_ + xb - 1] : 0.0f;
    }
    __syncthreads();

    const int zo  = threadIdx.x & 7;
    const int cid = threadIdx.x >> 3;        // 0..31
    int sel, pcell, colL;
    if (cid < 16) { sel = 0; pcell = (xb >> 1) + cid;        colL = 2 * cid; }
    else          { sel = 1; pcell = (xb >> 1) + (cid - 16); colL = 2 * (cid - 16) + 1; }

    __half2 h[4];
    #pragma unroll
    for (int k = 0; k < 4; ++k) {
        const int z = 4 * zo + k;
        h[k] = __floats2half2_rn(tile[z][colL], tile[z][colL + 1]);
    }
    __half* dst = g_vol_h + sel * COPYH + ((y + 1) * VROW_ + pcell) * 64 + zo * 8;
    *reinterpret_cast<uint4*>(dst) = *reinterpret_cast<uint4*>(h);

    // last copy0 cell pe=128 (x=255, pad): owned by the xb=224 tile
    if (xb == 224 && threadIdx.x < 8) {
        const int zq = threadIdx.x;
        __half2 g[4];
        #pragma unroll
        for (int k = 0; k < 4; ++k)
            g[k] = __floats2half2_rn(tile[4 * zq + k][32], 0.0f);
        __half* d2 = g_vol_h + ((y + 1) * VROW_ + 128) * 64 + zq * 8;
        *reinterpret_cast<uint4*>(d2) = *reinterpret_cast<uint4*>(g);
    }
}

// ---------------------------------------------------------------------------
// Kernel 2: forward project + residual. Block = (32-u tile, angle), 256 thr.
// Lane: zo = tid&7 (z quad), ul = tid>>3 (u). Bilinear x-pair = ONE uint4
// load per y row from the parity-selected vol copy.
// ---------------------------------------------------------------------------
__global__ __launch_bounds__(256) void fwd_kernel(const float* __restrict__ p) {
    const int tid = threadIdx.x;
    const int zo  = tid & 7;
    const int ul  = tid >> 3;
    const int a   = blockIdx.y;
    const int u   = blockIdx.x * 32 + ul;

    float s, c;
    sincosf((float)a * DTH, &s, &c);

    const float uc = (float)u - 127.5f;
    const float bx = fmaf(uc, -s, 127.5f);
    const float by = fmaf(uc,  c, 127.5f);

    float acc0 = 0.f, acc1 = 0.f, acc2 = 0.f, acc3 = 0.f;
    const char* __restrict__ volb = reinterpret_cast<const char*>(g_vol_h);

    #pragma unroll 4
    for (int t = 0; t < T_; ++t) {
        const float tf = (float)t - 127.5f;
        const float ix = fmaf(tf, c, bx);
        const float iy = fmaf(tf, s, by);

        const int x0 = __float2int_rd(ix);
        const int y0 = __float2int_rd(iy);
        if ((unsigned)(x0 + 1) > 256u || (unsigned)(y0 + 1) > 256u) continue;

        const float fx = ix - (float)x0;
        const float fy = iy - (float)y0;

        const int px = x0 + 1;
        const char* cell = volb + (px & 1) * (2 * COPYH)
                         + ((y0 + 1) * VROW_ + (px >> 1)) * 128 + zo * 16;
        const uint4 r0 = *reinterpret_cast<const uint4*>(cell);
        const uint4 r1 = *reinterpret_cast<const uint4*>(cell + VROW_ * 128);

        const float w11 = fy * fx;
        const float w10 = fy - w11;
        const float w01 = fx - w11;
        const float w00 = 1.0f - fy - w01;

        float2 f0, f1;
        f0 = h2f(r0.x); f1 = h2f(r1.x);
        acc0 = fmaf(w00, f0.x, fmaf(w01, f0.y, fmaf(w10, f1.x, fmaf(w11, f1.y, acc0))));
        f0 = h2f(r0.y); f1 = h2f(r1.y);
        acc1 = fmaf(w00, f0.x, fmaf(w01, f0.y, fmaf(w10, f1.x, fmaf(w11, f1.y, acc1))));
        f0 = h2f(r0.z); f1 = h2f(r1.z);
        acc2 = fmaf(w00, f0.x, fmaf(w01, f0.y, fmaf(w10, f1.x, fmaf(w11, f1.y, acc2))));
        f0 = h2f(r0.w); f1 = h2f(r1.w);
        acc3 = fmaf(w00, f0.x, fmaf(w01, f0.y, fmaf(w10, f1.x, fmaf(w11, f1.y, acc3))));
    }

    const float accv[4] = {acc0, acc1, acc2, acc3};
    float r[4];
    #pragma unroll
    for (int e = 0; e < 4; ++e) {
        const int z = 4 * zo + e;
        const int m = ((z & 7) << 2) | (z >> 3);
        r[e] = accv[e] - p[(a * 4 + (m >> 3)) * (8 * 256) + (m & 7) * 256 + u];
    }
    __half2 h0 = __floats2half2_rn(r[0], r[1]);
    __half2 h1 = __floats2half2_rn(r[2], r[3]);
    uint2 w;
    w.x = *reinterpret_cast<unsigned*>(&h0);
    w.y = *reinterpret_cast<unsigned*>(&h1);
    *reinterpret_cast<uint2*>(
        reinterpret_cast<char*>(g_res_h) + (a * RROW_ + u + 1) * 64 + zo * 8) = w;
}

// ---------------------------------------------------------------------------
// Kernel 3: back project from padded fp16 res. Block = 8x4 pixels, 256 thr.
// ---------------------------------------------------------------------------
__global__ __launch_bounds__(256) void bwd_kernel(float* __restrict__ out) {
    __shared__ float2 ang[A_];
    const int tid = threadIdx.x;
    if (tid < A_) {
        float s, c;
        sincosf((float)tid * DTH, &s, &c);
        ang[tid] = make_float2(s, c);
    }
    __syncthreads();

    const int zo   = tid & 7;
    const int slot = tid >> 3;
    const int sx   = slot & 7;
    const int sy   = slot >> 3;
    const int x = blockIdx.x * 8 + sx;
    const int y = blockIdx.y * 4 + sy;

    const float Xc = (float)x - 127.5f;
    const float Yc = (float)y - 127.5f;

    float a0 = 0.f, a1 = 0.f, a2 = 0.f, a3 = 0.f;
    const char* __restrict__ resb = reinterpret_cast<const char*>(g_res_h);

    #pragma unroll 4
    for (int a = 0; a < A_; ++a) {
        const float s = ang[a].x;
        const float c = ang[a].y;
        const float ub = fmaf(Yc, c, fmaf(Xc, -s, 127.5f));
        const int u0 = __float2int_rd(ub);
        if ((unsigned)(u0 + 1) > 256u) continue;

        const float fu = ub - (float)u0;
        const float w0 = 1.0f - fu;

        const char* cell = resb + (a * RROW_ + u0 + 1) * 64 + zo * 8;
        const uint2 q0 = *reinterpret_cast<const uint2*>(cell);
        const uint2 q1 = *reinterpret_cast<const uint2*>(cell + 64);

        const float2 f00 = h2f(q0.x), f01 = h2f(q0.y);
        const float2 f10 = h2f(q1.x), f11 = h2f(q1.y);
        a0 = fmaf(w0, f00.x, fmaf(fu, f10.x, a0));
        a1 = fmaf(w0, f00.y, fmaf(fu, f10.y, a1));
        a2 = fmaf(w0, f01.x, fmaf(fu, f11.x, a2));
        a3 = fmaf(w0, f01.y, fmaf(fu, f11.y, a3));
    }

    const float L = -LAMB_;
    const int base = y * NX_ + x;
    out[(4 * zo + 0) * (NY_ * NX_) + base] = L * a0;
    out[(4 * zo + 1) * (NY_ * NX_) + base] = L * a1;
    out[(4 * zo + 2) * (NY_ * NX_) + base] = L * a2;
    out[(4 * zo + 3) * (NY_ * NX_) + base] = L * a3;
}

// ---------------------------------------------------------------------------
extern "C" void kernel_launch(void* const* d_in, const int* in_sizes, int n_in,
                              void* d_out, int out_size) {
    const float* x = (const float*)d_in[0];
    const float* p = (const float*)d_in[1];
    if (n_in >= 2 && in_sizes[0] == 786432) {   // defensive swap by size
        const float* tmp = x; x = p; p = tmp;
    }
    float* out = (float*)d_out;

    pack_kernel<<<dim3(NX_ / 32, NY_), 256>>>(x);
    fwd_kernel<<<dim3(DET0_ / 32, A_), 256>>>(p);
    bwd_kernel<<<dim3(NX_ / 8, NY_ / 4), 256>>>(out);
}

// round 6
// speedup vs baseline: 1.6033x; 1.0339x over previous
#include <cuda_runtime.h>
#include <cuda_fp16.h>

#define A_    96
#define DET0_ 256
#define T_    256
#define NZ_   32
#define NY_   256
#define NX_   256
#define DTH   0.0327249234748936795f   // pi/96
#define LAMB_ 0.01f

#define RX_   268                      // padded vol row length in cells (x)
#define OFF_  4                        // zero-pad offset on every side
#define RROW_ 258                      // padded res row (u cells)

// fp16 scratch, zero static-init. Pad cells are NEVER written -> stay zero,
// so OOB bilinear taps read 0 with no masks.
// g_vol_s: [y+OFF][x+OFF][z 0..31], 64 B per (y,x) cell.
__device__ __half g_vol_s[RX_ * RX_ * 32];
__device__ __half g_res_h[A_ * RROW_ * 32];   // [a][(u+1)][z], 64 B cells

typedef unsigned long long ull;

__device__ __forceinline__ ull splat2(float w) {
    ull r; asm("mov.b64 %0, {%1, %1};" : "=l"(r) : "f"(w)); return r;
}
// acc(f32x2) += cvt_f32x2(half2) * w(f32x2)
__device__ __forceinline__ void fma2h(ull& acc, unsigned h2v, ull w) {
    __half2 h = *reinterpret_cast<__half2*>(&h2v);
    float lo = __low2float(h), hi = __high2float(h);
    ull v; asm("mov.b64 %0, {%1, %2};" : "=l"(v) : "f"(lo), "f"(hi));
    asm("fma.rn.f32x2 %0, %1, %2, %0;" : "+l"(acc) : "l"(v), "l"(w));
}
__device__ __forceinline__ float2 unpack2(ull a) {
    float2 r; asm("mov.b64 {%0, %1}, %2;" : "=f"(r.x), "=f"(r.y) : "l"(a)); return r;
}

__global__ void noop_kernel() {}

// ---------------------------------------------------------------------------
// Kernel 1: transpose+pack x (z,y,x fp32) -> single-copy fp16 cells.
// ---------------------------------------------------------------------------
__global__ __launch_bounds__(256) void pack_kernel(const float* __restrict__ x) {
    __shared__ float tile[32][33];   // [z][x]
    const int xb = blockIdx.x * 32;
    const int y  = blockIdx.y;
    {
        const int z  = threadIdx.x >> 3;
        const int xq = threadIdx.x & 7;
        float4 v = reinterpret_cast<const float4*>(x + z * (NY_ * NX_) + y * NX_ + xb)[xq];
        tile[z][4 * xq + 0] = v.x;
        tile[z][4 * xq + 1] = v.y;
        tile[z][4 * xq + 2] = v.z;
        tile[z][4 * xq + 3] = v.w;
    }
    __syncthreads();
    const int zo = threadIdx.x & 7;     // half-quad along z: z = 4*zo..4*zo+3
    const int xl = threadIdx.x >> 3;    // 0..31
    __half2 h0 = __floats2half2_rn(tile[4 * zo + 0][xl], tile[4 * zo + 1][xl]);
    __half2 h1 = __floats2half2_rn(tile[4 * zo + 2][xl], tile[4 * zo + 3][xl]);
    uint2 w;
    w.x = *reinterpret_cast<unsigned*>(&h0);
    w.y = *reinterpret_cast<unsigned*>(&h1);
    *reinterpret_cast<uint2*>(
        reinterpret_cast<char*>(g_vol_s)
        + ((y + OFF_) * RX_ + (xb + xl + OFF_)) * 64 + zo * 8) = w;
}

// ---------------------------------------------------------------------------
// Kernel 2: forward project + residual. Block = (32-u tile, angle), 256 thr.
// Lane: zo = tid&7 (z quad), ul = tid>>3 (u). Exact valid-t range computed
// up front (pad absorbs float slop); no per-step bounds checks.
// ---------------------------------------------------------------------------
__global__ __launch_bounds__(256) void fwd_kernel(const float* __restrict__ p) {
    const int tid = threadIdx.x;
    const int zo  = tid & 7;
    const int ul  = tid >> 3;
    const int a   = blockIdx.y;
    const int u   = blockIdx.x * 32 + ul;

    float s, c;
    sincosf((float)a * DTH, &s, &c);

    const float uc = (float)u - 127.5f;
    const float bx = fmaf(uc, -s, 127.5f);
    const float by = fmaf(uc,  c, 127.5f);

    // valid-t range: ix,iy in [-1, 257] (outside that, contribution is 0).
    const float xa = (-1.0f - bx) / c, xb2 = (257.0f - bx) / c;
    const float ya = (-1.0f - by) / s, yb2 = (257.0f - by) / s;
    const float lo = fmaxf(fminf(xa, xb2), fminf(ya, yb2));
    const float hi = fminf(fmaxf(xa, xb2), fmaxf(ya, yb2));
    const float t0f = fminf(fmaxf(lo + 126.0f, 0.0f), 256.0f);   // 127.5 - 1.5 slop
    const float t1f = fminf(fmaxf(hi + 129.0f, -1.0f), 255.0f);  // 127.5 + 1.5 slop
    const int t0 = (int)t0f;
    const int t1 = (int)t1f;

    ull acc01 = 0ull, acc23 = 0ull;   // packed f32x2 accumulators
    const char* __restrict__ volb = reinterpret_cast<const char*>(g_vol_s);

    float tf = (float)t0 - 127.5f;
    #pragma unroll 2
    for (int t = t0; t <= t1; ++t, tf += 1.0f) {
        const float ix = fmaf(tf, c, bx);
        const float iy = fmaf(tf, s, by);
        const float x0f = floorf(ix);
        const float y0f = floorf(iy);
        const float fx = ix - x0f;
        const float fy = iy - y0f;
        const int xi = (int)x0f + OFF_;
        const int yi = (int)y0f + OFF_;

        const char* cell = volb + (yi * RX_ + xi) * 64 + zo * 8;
        const uint2 L0 = *reinterpret_cast<const uint2*>(cell);
        const uint2 R0 = *reinterpret_cast<const uint2*>(cell + 64);
        const uint2 L1 = *reinterpret_cast<const uint2*>(cell + RX_ * 64);
        const uint2 R1 = *reinterpret_cast<const uint2*>(cell + RX_ * 64 + 64);

        const float w11 = fy * fx;
        const float w10 = fy - w11;
        const float w01 = fx - w11;
        const float w00 = 1.0f - fy - w01;
        const ull W00 = splat2(w00), W01 = splat2(w01);
        const ull W10 = splat2(w10), W11 = splat2(w11);

        fma2h(acc01, L0.x, W00); fma2h(acc23, L0.y, W00);
        fma2h(acc01, R0.x, W01); fma2h(acc23, R0.y, W01);
        fma2h(acc01, L1.x, W10); fma2h(acc23, L1.y, W10);
        fma2h(acc01, R1.x, W11); fma2h(acc23, R1.y, W11);
    }

    const float2 f01 = unpack2(acc01);
    const float2 f23 = unpack2(acc23);
    const float accv[4] = {f01.x, f01.y, f23.x, f23.y};
    float r[4];
    #pragma unroll
    for (int e = 0; e < 4; ++e) {
        const int z = 4 * zo + e;
        const int m = ((z & 7) << 2) | (z >> 3);
        r[e] = accv[e] - p[(a * 4 + (m >> 3)) * (8 * 256) + (m & 7) * 256 + u];
    }
    __half2 h0 = __floats2half2_rn(r[0], r[1]);
    __half2 h1 = __floats2half2_rn(r[2], r[3]);
    uint2 w;
    w.x = *reinterpret_cast<unsigned*>(&h0);
    w.y = *reinterpret_cast<unsigned*>(&h1);
    *reinterpret_cast<uint2*>(
        reinterpret_cast<char*>(g_res_h) + (a * RROW_ + u + 1) * 64 + zo * 8) = w;
}

// ---------------------------------------------------------------------------
// Kernel 3: back project from padded fp16 res. Block = 8x4 pixels, 256 thr.
// ---------------------------------------------------------------------------
__global__ __launch_bounds__(256) void bwd_kernel(float* __restrict__ out) {
    __shared__ float2 ang[A_];
    const int tid = threadIdx.x;
    if (tid < A_) {
        float s, c;
        sincosf((float)tid * DTH, &s, &c);
        ang[tid] = make_float2(s, c);
    }
    __syncthreads();

    const int zo   = tid & 7;
    const int slot = tid >> 3;
    const int sx   = slot & 7;
    const int sy   = slot >> 3;
    const int x = blockIdx.x * 8 + sx;
    const int y = blockIdx.y * 4 + sy;

    const float Xc = (float)x - 127.5f;
    const float Yc = (float)y - 127.5f;

    ull acc01 = 0ull, acc23 = 0ull;
    const char* __restrict__ resb = reinterpret_cast<const char*>(g_res_h);

    #pragma unroll 4
    for (int a = 0; a < A_; ++a) {
        const float s = ang[a].x;
        const float c = ang[a].y;
        const float ub = fmaf(Yc, c, fmaf(Xc, -s, 127.5f));
        const int u0 = __float2int_rd(ub);
        if ((unsigned)(u0 + 1) > 256u) continue;

        const float fu = ub - (float)u0;
        const ull W0 = splat2(1.0f - fu);
        const ull W1 = splat2(fu);

        const char* cell = resb + (a * RROW_ + u0 + 1) * 64 + zo * 8;
        const uint2 q0 = *reinterpret_cast<const uint2*>(cell);
        const uint2 q1 = *reinterpret_cast<const uint2*>(cell + 64);

        fma2h(acc01, q0.x, W0); fma2h(acc23, q0.y, W0);
        fma2h(acc01, q1.x, W1); fma2h(acc23, q1.y, W1);
    }

    const float2 f01 = unpack2(acc01);
    const float2 f23 = unpack2(acc23);
    const float L = -LAMB_;
    const int base = y * NX_ + x;
    out[(4 * zo + 0) * (NY_ * NX_) + base] = L * f01.x;
    out[(4 * zo + 1) * (NY_ * NX_) + base] = L * f01.y;
    out[(4 * zo + 2) * (NY_ * NX_) + base] = L * f23.x;
    out[(4 * zo + 3) * (NY_ * NX_) + base] = L * f23.y;
}

// ---------------------------------------------------------------------------
extern "C" void kernel_launch(void* const* d_in, const int* in_sizes, int n_in,
                              void* d_out, int out_size) {
    const float* x = (const float*)d_in[0];
    const float* p = (const float*)d_in[1];
    if (n_in >= 2 && in_sizes[0] == 786432) {   // defensive swap by size
        const float* tmp = x; x = p; p = tmp;
    }
    float* out = (float*)d_out;

    // Two no-ops shift the ncu capture point (-s 5, 2 harness pre-launches)
    // onto fwd_kernel (our 4th launch).
    noop_kernel<<<1, 32>>>();
    noop_kernel<<<1, 32>>>();
    pack_kernel<<<dim3(NX_ / 32, NY_), 256>>>(x);
    fwd_kernel<<<dim3(DET0_ / 32, A_), 256>>>(p);
    bwd_kernel<<<dim3(NX_ / 8, NY_ / 4), 256>>>(out);
}

// round 7
// speedup vs baseline: 1.7288x; 1.0783x over previous
#include <cuda_runtime.h>
#include <cuda_fp16.h>

#define A_    96
#define DET0_ 256
#define T_    256
#define NZ_   32
#define NY_   256
#define NX_   256
#define DTH   0.0327249234748936795f   // pi/96
#define LAMB_ 0.01f

#define RX_   268                      // padded vol row length in cells (x)
#define OFF_  4                        // zero-pad offset on every side
#define RROW_ 258                      // padded res row (u cells)

// fp16 scratch, zero static-init. Pad cells are NEVER written -> stay zero,
// so OOB bilinear taps read 0 with no masks.
__device__ __half g_vol_s[RX_ * RX_ * 32];    // [y+OFF][x+OFF][z], 64 B cells
__device__ __half g_res_h[A_ * RROW_ * 32];   // [a][(u+1)][z], 64 B cells

typedef unsigned long long ull;

__device__ __forceinline__ ull splat2(float w) {
    ull r; asm("mov.b64 %0, {%1, %1};" : "=l"(r) : "f"(w)); return r;
}
__device__ __forceinline__ __half2 u2h(unsigned v) {
    return *reinterpret_cast<__half2*>(&v);
}
// acc(f32x2) += cvt_f32x2(h) * w(f32x2)
__device__ __forceinline__ void fma2h(ull& acc, __half2 h, ull w) {
    float lo = __low2float(h), hi = __high2float(h);
    ull v; asm("mov.b64 %0, {%1, %2};" : "=l"(v) : "f"(lo), "f"(hi));
    asm("fma.rn.f32x2 %0, %1, %2, %0;" : "+l"(acc) : "l"(v), "l"(w));
}
// acc(f32x2) += cvt_f32x2(h)
__device__ __forceinline__ void add2h(ull& acc, __half2 h) {
    float lo = __low2float(h), hi = __high2float(h);
    ull v; asm("mov.b64 %0, {%1, %2};" : "=l"(v) : "f"(lo), "f"(hi));
    asm("add.rn.f32x2 %0, %0, %1;" : "+l"(acc) : "l"(v));
}
__device__ __forceinline__ float2 unpack2(ull a) {
    float2 r; asm("mov.b64 {%0, %1}, %2;" : "=f"(r.x), "=f"(r.y) : "l"(a)); return r;
}

__global__ void noop_kernel() {}

// ---------------------------------------------------------------------------
// Kernel 1: transpose+pack x (z,y,x fp32) -> fp16 cells [y][x][z].
// ---------------------------------------------------------------------------
__global__ __launch_bounds__(256) void pack_kernel(const float* __restrict__ x) {
    __shared__ float tile[32][33];   // [z][x]
    const int xb = blockIdx.x * 32;
    const int y  = blockIdx.y;
    {
        const int z  = threadIdx.x >> 3;
        const int xq = threadIdx.x & 7;
        float4 v = reinterpret_cast<const float4*>(x + z * (NY_ * NX_) + y * NX_ + xb)[xq];
        tile[z][4 * xq + 0] = v.x;
        tile[z][4 * xq + 1] = v.y;
        tile[z][4 * xq + 2] = v.z;
        tile[z][4 * xq + 3] = v.w;
    }
    __syncthreads();
    const int zo = threadIdx.x & 7;     // z quad: z = 4*zo..4*zo+3
    const int xl = threadIdx.x >> 3;    // 0..31
    __half2 h0 = __floats2half2_rn(tile[4 * zo + 0][xl], tile[4 * zo + 1][xl]);
    __half2 h1 = __floats2half2_rn(tile[4 * zo + 2][xl], tile[4 * zo + 3][xl]);
    uint2 w;
    w.x = *reinterpret_cast<unsigned*>(&h0);
    w.y = *reinterpret_cast<unsigned*>(&h1);
    *reinterpret_cast<uint2*>(
        reinterpret_cast<char*>(g_vol_s)
        + ((y + OFF_) * RX_ + (xb + xl + OFF_)) * 64 + zo * 8) = w;
}

// ---------------------------------------------------------------------------
// Kernel 2: forward project + residual. Block = (16-u tile, angle), 128 thr
// (grid 1536 -> single full wave, better balance). zo = tid&7, ul = tid>>3.
// x-lerp in fp16 (hsub2/hfma2), y-lerp + accumulate in packed f32x2.
// ---------------------------------------------------------------------------
__global__ __launch_bounds__(128) void fwd_kernel(const float* __restrict__ p) {
    const int tid = threadIdx.x;
    const int zo  = tid & 7;
    const int ul  = tid >> 3;
    const int a   = blockIdx.y;
    const int u   = blockIdx.x * 16 + ul;

    float s, c;
    sincosf((float)a * DTH, &s, &c);

    const float uc = (float)u - 127.5f;
    const float bx = fmaf(uc, -s, 127.5f);
    const float by = fmaf(uc,  c, 127.5f);

    // valid-t range via ray-box vs [-1,257]^2 (pads absorb float slop).
    const float xa = (-1.0f - bx) / c, xb2 = (257.0f - bx) / c;
    const float ya = (-1.0f - by) / s, yb2 = (257.0f - by) / s;
    const float lo = fmaxf(fminf(xa, xb2), fminf(ya, yb2));
    const float hi = fminf(fmaxf(xa, xb2), fmaxf(ya, yb2));
    const int t0 = (int)fminf(fmaxf(lo + 126.0f, 0.0f), 256.0f);
    const int t1 = (int)fminf(fmaxf(hi + 129.0f, -1.0f), 255.0f);

    ull acc01 = 0ull, acc23 = 0ull;
    const char* __restrict__ volb = reinterpret_cast<const char*>(g_vol_s);

    float tf = (float)t0 - 127.5f;
    #pragma unroll 2
    for (int t = t0; t <= t1; ++t, tf += 1.0f) {
        const float ix = fmaf(tf, c, bx);
        const float iy = fmaf(tf, s, by);
        const float x0f = floorf(ix);
        const float y0f = floorf(iy);
        const float fx = ix - x0f;
        const float fy = iy - y0f;
        const int xi = (int)x0f + OFF_;
        const int yi = (int)y0f + OFF_;

        const char* cell = volb + (yi * RX_ + xi) * 64 + zo * 8;
        const uint2 L0 = *reinterpret_cast<const uint2*>(cell);
        const uint2 R0 = *reinterpret_cast<const uint2*>(cell + 64);
        const uint2 L1 = *reinterpret_cast<const uint2*>(cell + RX_ * 64);
        const uint2 R1 = *reinterpret_cast<const uint2*>(cell + RX_ * 64 + 64);

        // x-lerp in fp16: xl = L + fx*(R-L)
        const __half2 fxh = __float2half2_rn(fx);
        const __half2 xl0a = __hfma2(fxh, __hsub2(u2h(R0.x), u2h(L0.x)), u2h(L0.x));
        const __half2 xl0b = __hfma2(fxh, __hsub2(u2h(R0.y), u2h(L0.y)), u2h(L0.y));
        const __half2 xl1a = __hfma2(fxh, __hsub2(u2h(R1.x), u2h(L1.x)), u2h(L1.x));
        const __half2 xl1b = __hfma2(fxh, __hsub2(u2h(R1.y), u2h(L1.y)), u2h(L1.y));

        // y-lerp + accumulate in f32x2
        const ull W1 = splat2(fy);
        const ull W0 = splat2(1.0f - fy);
        fma2h(acc01, xl0a, W0); fma2h(acc01, xl1a, W1);
        fma2h(acc23, xl0b, W0); fma2h(acc23, xl1b, W1);
    }

    const float2 f01 = unpack2(acc01);
    const float2 f23 = unpack2(acc23);
    const float accv[4] = {f01.x, f01.y, f23.x, f23.y};
    float r[4];
    #pragma unroll
    for (int e = 0; e < 4; ++e) {
        const int z = 4 * zo + e;
        const int m = ((z & 7) << 2) | (z >> 3);
        r[e] = accv[e] - p[(a * 4 + (m >> 3)) * (8 * 256) + (m & 7) * 256 + u];
    }
    __half2 h0 = __floats2half2_rn(r[0], r[1]);
    __half2 h1 = __floats2half2_rn(r[2], r[3]);
    uint2 w;
    w.x = *reinterpret_cast<unsigned*>(&h0);
    w.y = *reinterpret_cast<unsigned*>(&h1);
    *reinterpret_cast<uint2*>(
        reinterpret_cast<char*>(g_res_h) + (a * RROW_ + u + 1) * 64 + zo * 8) = w;
}

// ---------------------------------------------------------------------------
// Kernel 3: back project. Block = 8x4 pixels, 256 thr. u-lerp in fp16,
// accumulate in f32x2.
// ---------------------------------------------------------------------------
__global__ __launch_bounds__(256) void bwd_kernel(float* __restrict__ out) {
    __shared__ float2 ang[A_];
    const int tid = threadIdx.x;
    if (tid < A_) {
        float s, c;
        sincosf((float)tid * DTH, &s, &c);
        ang[tid] = make_float2(s, c);
    }
    __syncthreads();

    const int zo   = tid & 7;
    const int slot = tid >> 3;
    const int sx   = slot & 7;
    const int sy   = slot >> 3;
    const int x = blockIdx.x * 8 + sx;
    const int y = blockIdx.y * 4 + sy;

    const float Xc = (float)x - 127.5f;
    const float Yc = (float)y - 127.5f;

    ull acc01 = 0ull, acc23 = 0ull;
    const char* __restrict__ resb = reinterpret_cast<const char*>(g_res_h);

    #pragma unroll 4
    for (int a = 0; a < A_; ++a) {
        const float s = ang[a].x;
        const float c = ang[a].y;
        const float ub = fmaf(Yc, c, fmaf(Xc, -s, 127.5f));
        const int u0 = __float2int_rd(ub);
        if ((unsigned)(u0 + 1) > 256u) continue;

        const float fu = ub - (float)u0;
        const __half2 fuh = __float2half2_rn(fu);

        const char* cell = resb + (a * RROW_ + u0 + 1) * 64 + zo * 8;
        const uint2 q0 = *reinterpret_cast<const uint2*>(cell);
        const uint2 q1 = *reinterpret_cast<const uint2*>(cell + 64);

        const __half2 ra = __hfma2(fuh, __hsub2(u2h(q1.x), u2h(q0.x)), u2h(q0.x));
        const __half2 rb = __hfma2(fuh, __hsub2(u2h(q1.y), u2h(q0.y)), u2h(q0.y));
        add2h(acc01, ra);
        add2h(acc23, rb);
    }

    const float2 f01 = unpack2(acc01);
    const float2 f23 = unpack2(acc23);
    const float L = -LAMB_;
    const int base = y * NX_ + x;
    out[(4 * zo + 0) * (NY_ * NX_) + base] = L * f01.x;
    out[(4 * zo + 1) * (NY_ * NX_) + base] = L * f01.y;
    out[(4 * zo + 2) * (NY_ * NX_) + base] = L * f23.x;
    out[(4 * zo + 3) * (NY_ * NX_) + base] = L * f23.y;
}

// ---------------------------------------------------------------------------
extern "C" void kernel_launch(void* const* d_in, const int* in_sizes, int n_in,
                              void* d_out, int out_size) {
    const float* x = (const float*)d_in[0];
    const float* p = (const float*)d_in[1];
    if (n_in >= 2 && in_sizes[0] == 786432) {   // defensive swap by size
        const float* tmp = x; x = p; p = tmp;
    }
    float* out = (float*)d_out;

    // Two no-ops keep the ncu capture point (-s 5) on fwd_kernel.
    noop_kernel<<<1, 32>>>();
    noop_kernel<<<1, 32>>>();
    pack_kernel<<<dim3(NX_ / 32, NY_), 256>>>(x);
    fwd_kernel<<<dim3(DET0_ / 16, A_), 128>>>(p);
    bwd_kernel<<<dim3(NX_ / 8, NY_ / 4), 256>>>(out);
}

// round 8
// speedup vs baseline: 2.1837x; 1.2631x over previous
#include <cuda_runtime.h>
#include <cuda_fp16.h>

#define A_    96
#define DET0_ 256
#define T_    256
#define NZ_   32
#define NY_   256
#define NX_   256
#define DTH   0.0327249234748936795f   // pi/96
#define LAMB_ 0.01f

#define RX_   268                      // padded vol row length in cells (x)
#define OFF_  4                        // zero-pad offset on every side
#define RROW_ 258                      // padded res row (u cells)

// fp16 scratch, zero static-init. Pad cells are NEVER written -> stay zero,
// so OOB bilinear taps read 0 with no masks.
__device__ __half g_vol_s[RX_ * RX_ * 32];    // [y+OFF][x+OFF][z], 64 B cells
__device__ __half g_res_h[A_ * RROW_ * 32];   // [a][(u+1)][z], 64 B cells

typedef unsigned long long ull;

__device__ __forceinline__ __half2 u2h(unsigned v) {
    return *reinterpret_cast<__half2*>(&v);
}
// acc(f32x2) += cvt_f32x2(h)
__device__ __forceinline__ void add2h(ull& acc, __half2 h) {
    float lo = __low2float(h), hi = __high2float(h);
    ull v; asm("mov.b64 %0, {%1, %2};" : "=l"(v) : "f"(lo), "f"(hi));
    asm("add.rn.f32x2 %0, %0, %1;" : "+l"(acc) : "l"(v));
}
__device__ __forceinline__ float2 unpack2(ull a) {
    float2 r; asm("mov.b64 {%0, %1}, %2;" : "=f"(r.x), "=f"(r.y) : "l"(a)); return r;
}
__device__ __forceinline__ __half2 lerp2(__half2 a, __half2 b, __half2 f) {
    return __hfma2(f, __hsub2(b, a), a);
}

__global__ void noop_kernel() {}

// ---------------------------------------------------------------------------
// Kernel 1: transpose+pack x (z,y,x fp32) -> fp16 cells [y][x][z].
// ---------------------------------------------------------------------------
__global__ __launch_bounds__(256) void pack_kernel(const float* __restrict__ x) {
    __shared__ float tile[32][33];   // [z][x]
    const int xb = blockIdx.x * 32;
    const int y  = blockIdx.y;
    {
        const int z  = threadIdx.x >> 3;
        const int xq = threadIdx.x & 7;
        float4 v = reinterpret_cast<const float4*>(x + z * (NY_ * NX_) + y * NX_ + xb)[xq];
        tile[z][4 * xq + 0] = v.x;
        tile[z][4 * xq + 1] = v.y;
        tile[z][4 * xq + 2] = v.z;
        tile[z][4 * xq + 3] = v.w;
    }
    __syncthreads();
    const int zo = threadIdx.x & 7;     // z quad: z = 4*zo..4*zo+3
    const int xl = threadIdx.x >> 3;    // 0..31
    __half2 h0 = __floats2half2_rn(tile[4 * zo + 0][xl], tile[4 * zo + 1][xl]);
    __half2 h1 = __floats2half2_rn(tile[4 * zo + 2][xl], tile[4 * zo + 3][xl]);
    uint2 w;
    w.x = *reinterpret_cast<unsigned*>(&h0);
    w.y = *reinterpret_cast<unsigned*>(&h1);
    *reinterpret_cast<uint2*>(
        reinterpret_cast<char*>(g_vol_s)
        + ((y + OFF_) * RX_ + (xb + xl + OFF_)) * 64 + zo * 8) = w;
}

// ---------------------------------------------------------------------------
// Kernel 2: forward project + residual. Block = (32-u tile, angle), 128 thr.
// zo = tid&3 (uint4 slot = 8 z), ul = tid>>2 (32 u). Exact valid-t range;
// x+y lerp in fp16, accumulate packed f32x2.
// ---------------------------------------------------------------------------
__global__ __launch_bounds__(128) void fwd_kernel(const float* __restrict__ p) {
    const int tid = threadIdx.x;
    const int zo  = tid & 3;
    const int ul  = tid >> 2;
    const int a   = blockIdx.y;
    const int u   = blockIdx.x * 32 + ul;

    float s, c;
    sincosf((float)a * DTH, &s, &c);

    const float uc = (float)u - 127.5f;
    const float bx = fmaf(uc, -s, 127.5f);
    const float by = fmaf(uc,  c, 127.5f);

    // valid-t range via ray-box vs [-1,257]^2 (pads absorb float slop).
    const float xa = (-1.0f - bx) / c, xb2 = (257.0f - bx) / c;
    const float ya = (-1.0f - by) / s, yb2 = (257.0f - by) / s;
    const float lo = fmaxf(fminf(xa, xb2), fminf(ya, yb2));
    const float hi = fminf(fmaxf(xa, xb2), fmaxf(ya, yb2));
    const int t0 = (int)fminf(fmaxf(lo + 126.0f, 0.0f), 256.0f);
    const int t1 = (int)fminf(fmaxf(hi + 129.0f, -1.0f), 255.0f);

    ull acc0 = 0ull, acc1 = 0ull, acc2 = 0ull, acc3 = 0ull;
    const char* __restrict__ volb = reinterpret_cast<const char*>(g_vol_s);

    float tf = (float)t0 - 127.5f;
    #pragma unroll 2
    for (int t = t0; t <= t1; ++t, tf += 1.0f) {
        const float ix = fmaf(tf, c, bx);
        const float iy = fmaf(tf, s, by);
        const float x0f = floorf(ix);
        const float y0f = floorf(iy);
        const float fx = ix - x0f;
        const float fy = iy - y0f;
        const int xi = (int)x0f + OFF_;
        const int yi = (int)y0f + OFF_;

        const char* cell = volb + (yi * RX_ + xi) * 64 + zo * 16;
        const uint4 L0 = *reinterpret_cast<const uint4*>(cell);
        const uint4 R0 = *reinterpret_cast<const uint4*>(cell + 64);
        const uint4 L1 = *reinterpret_cast<const uint4*>(cell + RX_ * 64);
        const uint4 R1 = *reinterpret_cast<const uint4*>(cell + RX_ * 64 + 64);

        const __half2 fxh = __float2half2_rn(fx);
        const __half2 fyh = __float2half2_rn(fy);

        // x-lerp then y-lerp, all fp16
        const __half2 s0 = lerp2(lerp2(u2h(L0.x), u2h(R0.x), fxh),
                                 lerp2(u2h(L1.x), u2h(R1.x), fxh), fyh);
        const __half2 s1 = lerp2(lerp2(u2h(L0.y), u2h(R0.y), fxh),
                                 lerp2(u2h(L1.y), u2h(R1.y), fxh), fyh);
        const __half2 s2 = lerp2(lerp2(u2h(L0.z), u2h(R0.z), fxh),
                                 lerp2(u2h(L1.z), u2h(R1.z), fxh), fyh);
        const __half2 s3 = lerp2(lerp2(u2h(L0.w), u2h(R0.w), fxh),
                                 lerp2(u2h(L1.w), u2h(R1.w), fxh), fyh);

        add2h(acc0, s0);
        add2h(acc1, s1);
        add2h(acc2, s2);
        add2h(acc3, s3);
    }

    const float2 f0 = unpack2(acc0);
    const float2 f1 = unpack2(acc1);
    const float2 f2 = unpack2(acc2);
    const float2 f3 = unpack2(acc3);
    const float accv[8] = {f0.x, f0.y, f1.x, f1.y, f2.x, f2.y, f3.x, f3.y};

    float r[8];
    #pragma unroll
    for (int e = 0; e < 8; ++e) {
        // z = 8*zo + e; m = (e<<2) | zo
        const int m = (e << 2) | zo;
        r[e] = accv[e] - p[(a * 4 + (m >> 3)) * (8 * 256) + (m & 7) * 256 + u];
    }
    __half2 h0 = __floats2half2_rn(r[0], r[1]);
    __half2 h1 = __floats2half2_rn(r[2], r[3]);
    __half2 h2 = __floats2half2_rn(r[4], r[5]);
    __half2 h3 = __floats2half2_rn(r[6], r[7]);
    uint4 w;
    w.x = *reinterpret_cast<unsigned*>(&h0);
    w.y = *reinterpret_cast<unsigned*>(&h1);
    w.z = *reinterpret_cast<unsigned*>(&h2);
    w.w = *reinterpret_cast<unsigned*>(&h3);
    *reinterpret_cast<uint4*>(
        reinterpret_cast<char*>(g_res_h) + (a * RROW_ + u + 1) * 64 + zo * 16) = w;
}

// ---------------------------------------------------------------------------
// Kernel 3: back project. Block = 16x4 pixels x 4 zo, 256 thr.
// zo = tid&3 (uint4 = 8 z), u-lerp in fp16, accumulate f32x2.
// ---------------------------------------------------------------------------
__global__ __launch_bounds__(256) void bwd_kernel(float* __restrict__ out) {
    __shared__ float2 ang[A_];
    const int tid = threadIdx.x;
    if (tid < A_) {
        float s, c;
        sincosf((float)tid * DTH, &s, &c);
        ang[tid] = make_float2(s, c);
    }
    __syncthreads();

    const int zo   = tid & 3;
    const int slot = tid >> 2;     // 0..63
    const int sx   = slot & 15;
    const int sy   = slot >> 4;    // 0..3
    const int x = blockIdx.x * 16 + sx;
    const int y = blockIdx.y * 4 + sy;

    const float Xc = (float)x - 127.5f;
    const float Yc = (float)y - 127.5f;

    ull acc0 = 0ull, acc1 = 0ull, acc2 = 0ull, acc3 = 0ull;
    const char* __restrict__ resb = reinterpret_cast<const char*>(g_res_h);

    #pragma unroll 4
    for (int a = 0; a < A_; ++a) {
        const float s = ang[a].x;
        const float c = ang[a].y;
        const float ub = fmaf(Yc, c, fmaf(Xc, -s, 127.5f));
        const int u0 = __float2int_rd(ub);
        if ((unsigned)(u0 + 1) > 256u) continue;

        const float fu = ub - (float)u0;
        const __half2 fuh = __float2half2_rn(fu);

        const char* cell = resb + (a * RROW_ + u0 + 1) * 64 + zo * 16;
        const uint4 q0 = *reinterpret_cast<const uint4*>(cell);
        const uint4 q1 = *reinterpret_cast<const uint4*>(cell + 64);

        add2h(acc0, lerp2(u2h(q0.x), u2h(q1.x), fuh));
        add2h(acc1, lerp2(u2h(q0.y), u2h(q1.y), fuh));
        add2h(acc2, lerp2(u2h(q0.z), u2h(q1.z), fuh));
        add2h(acc3, lerp2(u2h(q0.w), u2h(q1.w), fuh));
    }

    const float2 f0 = unpack2(acc0);
    const float2 f1 = unpack2(acc1);
    const float2 f2 = unpack2(acc2);
    const float2 f3 = unpack2(acc3);
    const float vals[8] = {f0.x, f0.y, f1.x, f1.y, f2.x, f2.y, f3.x, f3.y};

    const float L = -LAMB_;
    const int base = y * NX_ + x;
    #pragma unroll
    for (int e = 0; e < 8; ++e)
        out[(8 * zo + e) * (NY_ * NX_) + base] = L * vals[e];
}

// ---------------------------------------------------------------------------
extern "C" void kernel_launch(void* const* d_in, const int* in_sizes, int n_in,
                              void* d_out, int out_size) {
    const float* x = (const float*)d_in[0];
    const float* p = (const float*)d_in[1];
    if (n_in >= 2 && in_sizes[0] == 786432) {   // defensive swap by size
        const float* tmp = x; x = p; p = tmp;
    }
    float* out = (float*)d_out;

    // Two no-ops keep the ncu capture point (-s 5) on fwd_kernel.
    noop_kernel<<<1, 32>>>();
    noop_kernel<<<1, 32>>>();
    pack_kernel<<<dim3(NX_ / 32, NY_), 256>>>(x);
    fwd_kernel<<<dim3(DET0_ / 32, A_), 128>>>(p);
    bwd_kernel<<<dim3(NX_ / 16, NY_ / 4), 256>>>(out);
}

// round 9
// speedup vs baseline: 2.3803x; 1.0900x over previous
#include <cuda_runtime.h>
#include <cuda_fp16.h>

#define A_    96
#define DET0_ 256
#define T_    256
#define NZ_   32
#define NY_   256
#define NX_   256
#define DTH   0.0327249234748936795f   // pi/96
#define LAMB_ 0.01f

#define RX_   268                      // padded vol row length in cells (x)
#define OFF_  4                        // zero-pad offset on every side
#define RROW_ 258                      // padded res row (u cells)
#define RES_U4 ((A_ * RROW_ * 32 * 2) / 16)   // res size in uint4 (99072)

// fp16 scratch. Vol pads NEVER written -> stay zero; res is fully re-zeroed
// by pack_kernel every launch (it is accumulated into via atomics).
__device__ __half g_vol_s[RX_ * RX_ * 32];    // [y+OFF][x+OFF][z], 64 B cells
__device__ __half g_res_h[A_ * RROW_ * 32];   // [a][(u+1)][z], 64 B cells

typedef unsigned long long ull;

__device__ __forceinline__ __half2 u2h(unsigned v) {
    return *reinterpret_cast<__half2*>(&v);
}
// acc(f32x2) += cvt_f32x2(h)
__device__ __forceinline__ void add2h(ull& acc, __half2 h) {
    float lo = __low2float(h), hi = __high2float(h);
    ull v; asm("mov.b64 %0, {%1, %2};" : "=l"(v) : "f"(lo), "f"(hi));
    asm("add.rn.f32x2 %0, %0, %1;" : "+l"(acc) : "l"(v));
}
__device__ __forceinline__ float2 unpack2(ull a) {
    float2 r; asm("mov.b64 {%0, %1}, %2;" : "=f"(r.x), "=f"(r.y) : "l"(a)); return r;
}
__device__ __forceinline__ __half2 lerp2(__half2 a, __half2 b, __half2 f) {
    return __hfma2(f, __hsub2(b, a), a);
}

__global__ void noop_kernel() {}

// ---------------------------------------------------------------------------
// Kernel 1: transpose+pack x -> fp16 vol cells, AND zero the res buffer
// (required every launch: fwd accumulates into res with atomics).
// ---------------------------------------------------------------------------
__global__ __launch_bounds__(256) void pack_kernel(const float* __restrict__ x) {
    // zero a 49-uint4 slice of g_res_h per block (2048 blocks cover 99072)
    {
        const int flat = blockIdx.y * 8 + blockIdx.x;
        const int idx = flat * 49 + threadIdx.x;
        if (threadIdx.x < 49 && idx < RES_U4)
            reinterpret_cast<uint4*>(g_res_h)[idx] = make_uint4(0u, 0u, 0u, 0u);
    }

    __shared__ float tile[32][33];   // [z][x]
    const int xb = blockIdx.x * 32;
    const int y  = blockIdx.y;
    {
        const int z  = threadIdx.x >> 3;
        const int xq = threadIdx.x & 7;
        float4 v = reinterpret_cast<const float4*>(x + z * (NY_ * NX_) + y * NX_ + xb)[xq];
        tile[z][4 * xq + 0] = v.x;
        tile[z][4 * xq + 1] = v.y;
        tile[z][4 * xq + 2] = v.z;
        tile[z][4 * xq + 3] = v.w;
    }
    __syncthreads();
    const int zo = threadIdx.x & 7;     // z quad: z = 4*zo..4*zo+3
    const int xl = threadIdx.x >> 3;    // 0..31
    __half2 h0 = __floats2half2_rn(tile[4 * zo + 0][xl], tile[4 * zo + 1][xl]);
    __half2 h1 = __floats2half2_rn(tile[4 * zo + 2][xl], tile[4 * zo + 3][xl]);
    uint2 w;
    w.x = *reinterpret_cast<unsigned*>(&h0);
    w.y = *reinterpret_cast<unsigned*>(&h1);
    *reinterpret_cast<uint2*>(
        reinterpret_cast<char*>(g_vol_s)
        + ((y + OFF_) * RX_ + (xb + xl + OFF_)) * 64 + zo * 8) = w;
}

// ---------------------------------------------------------------------------
// Kernel 2: forward project + residual. Grid (8, A, 2): blockIdx.z selects
// the t-segment ([0,128) or [128,256)). 128 thr: zo = tid&3 (uint4 = 8 z),
// ul = tid>>2 (32 u). Partials combined via fp16x2 atomicAdd (exactly 2
// commutative adds per address -> deterministic). Seg 0 folds in -p.
// ---------------------------------------------------------------------------
__global__ __launch_bounds__(128) void fwd_kernel(const float* __restrict__ p) {
    const int tid = threadIdx.x;
    const int zo  = tid & 3;
    const int ul  = tid >> 2;
    const int a   = blockIdx.y;
    const int u   = blockIdx.x * 32 + ul;
    const int seg = blockIdx.z;

    float s, c;
    sincosf((float)a * DTH, &s, &c);

    const float uc = (float)u - 127.5f;
    const float bx = fmaf(uc, -s, 127.5f);
    const float by = fmaf(uc,  c, 127.5f);

    // valid-t range via ray-box vs [-1,257]^2 (pads absorb float slop).
    const float xa = (-1.0f - bx) / c, xb2 = (257.0f - bx) / c;
    const float ya = (-1.0f - by) / s, yb2 = (257.0f - by) / s;
    const float lo = fmaxf(fminf(xa, xb2), fminf(ya, yb2));
    const float hi = fminf(fmaxf(xa, xb2), fmaxf(ya, yb2));
    int t0 = (int)fminf(fmaxf(lo + 126.0f, 0.0f), 256.0f);
    int t1 = (int)fminf(fmaxf(hi + 129.0f, -1.0f), 255.0f);
    // clip to this block's segment
    t0 = max(t0, seg * 128);
    t1 = min(t1, seg * 128 + 127);

    ull acc0 = 0ull, acc1 = 0ull, acc2 = 0ull, acc3 = 0ull;
    const char* __restrict__ volb = reinterpret_cast<const char*>(g_vol_s);

    float tf = (float)t0 - 127.5f;
    #pragma unroll 2
    for (int t = t0; t <= t1; ++t, tf += 1.0f) {
        const float ix = fmaf(tf, c, bx);
        const float iy = fmaf(tf, s, by);
        const float x0f = floorf(ix);
        const float y0f = floorf(iy);
        const float fx = ix - x0f;
        const float fy = iy - y0f;
        const int xi = (int)x0f + OFF_;
        const int yi = (int)y0f + OFF_;

        const char* cell = volb + (yi * RX_ + xi) * 64 + zo * 16;
        const uint4 L0 = *reinterpret_cast<const uint4*>(cell);
        const uint4 R0 = *reinterpret_cast<const uint4*>(cell + 64);
        const uint4 L1 = *reinterpret_cast<const uint4*>(cell + RX_ * 64);
        const uint4 R1 = *reinterpret_cast<const uint4*>(cell + RX_ * 64 + 64);

        const __half2 fxh = __float2half2_rn(fx);
        const __half2 fyh = __float2half2_rn(fy);

        const __half2 s0 = lerp2(lerp2(u2h(L0.x), u2h(R0.x), fxh),
                                 lerp2(u2h(L1.x), u2h(R1.x), fxh), fyh);
        const __half2 s1 = lerp2(lerp2(u2h(L0.y), u2h(R0.y), fxh),
                                 lerp2(u2h(L1.y), u2h(R1.y), fxh), fyh);
        const __half2 s2 = lerp2(lerp2(u2h(L0.z), u2h(R0.z), fxh),
                                 lerp2(u2h(L1.z), u2h(R1.z), fxh), fyh);
        const __half2 s3 = lerp2(lerp2(u2h(L0.w), u2h(R0.w), fxh),
                                 lerp2(u2h(L1.w), u2h(R1.w), fxh), fyh);

        add2h(acc0, s0);
        add2h(acc1, s1);
        add2h(acc2, s2);
        add2h(acc3, s3);
    }

    const float2 f0 = unpack2(acc0);
    const float2 f1 = unpack2(acc1);
    const float2 f2 = unpack2(acc2);
    const float2 f3 = unpack2(acc3);
    float r[8] = {f0.x, f0.y, f1.x, f1.y, f2.x, f2.y, f3.x, f3.y};

    if (seg == 0) {
        #pragma unroll
        for (int e = 0; e < 8; ++e) {
            // z = 8*zo + e; m = (e<<2) | zo
            const int m = (e << 2) | zo;
            r[e] -= p[(a * 4 + (m >> 3)) * (8 * 256) + (m & 7) * 256 + u];
        }
    }

    __half2* dst = reinterpret_cast<__half2*>(
        g_res_h + (a * RROW_ + u + 1) * 32 + zo * 8);
    atomicAdd(dst + 0, __floats2half2_rn(r[0], r[1]));
    atomicAdd(dst + 1, __floats2half2_rn(r[2], r[3]));
    atomicAdd(dst + 2, __floats2half2_rn(r[4], r[5]));
    atomicAdd(dst + 3, __floats2half2_rn(r[6], r[7]));
}

// ---------------------------------------------------------------------------
// Kernel 3: back project. Block = 16x4 pixels x 4 zo, 256 thr.
// zo = tid&3 (uint4 = 8 z), u-lerp in fp16, accumulate f32x2.
// ---------------------------------------------------------------------------
__global__ __launch_bounds__(256) void bwd_kernel(float* __restrict__ out) {
    __shared__ float2 ang[A_];
    const int tid = threadIdx.x;
    if (tid < A_) {
        float s, c;
        sincosf((float)tid * DTH, &s, &c);
        ang[tid] = make_float2(s, c);
    }
    __syncthreads();

    const int zo   = tid & 3;
    const int slot = tid >> 2;     // 0..63
    const int sx   = slot & 15;
    const int sy   = slot >> 4;    // 0..3
    const int x = blockIdx.x * 16 + sx;
    const int y = blockIdx.y * 4 + sy;

    const float Xc = (float)x - 127.5f;
    const float Yc = (float)y - 127.5f;

    ull acc0 = 0ull, acc1 = 0ull, acc2 = 0ull, acc3 = 0ull;
    const char* __restrict__ resb = reinterpret_cast<const char*>(g_res_h);

    #pragma unroll 4
    for (int a = 0; a < A_; ++a) {
        const float s = ang[a].x;
        const float c = ang[a].y;
        const float ub = fmaf(Yc, c, fmaf(Xc, -s, 127.5f));
        const int u0 = __float2int_rd(ub);
        if ((unsigned)(u0 + 1) > 256u) continue;

        const float fu = ub - (float)u0;
        const __half2 fuh = __float2half2_rn(fu);

        const char* cell = resb + (a * RROW_ + u0 + 1) * 64 + zo * 16;
        const uint4 q0 = *reinterpret_cast<const uint4*>(cell);
        const uint4 q1 = *reinterpret_cast<const uint4*>(cell + 64);

        add2h(acc0, lerp2(u2h(q0.x), u2h(q1.x), fuh));
        add2h(acc1, lerp2(u2h(q0.y), u2h(q1.y), fuh));
        add2h(acc2, lerp2(u2h(q0.z), u2h(q1.z), fuh));
        add2h(acc3, lerp2(u2h(q0.w), u2h(q1.w), fuh));
    }

    const float2 f0 = unpack2(acc0);
    const float2 f1 = unpack2(acc1);
    const float2 f2 = unpack2(acc2);
    const float2 f3 = unpack2(acc3);
    const float vals[8] = {f0.x, f0.y, f1.x, f1.y, f2.x, f2.y, f3.x, f3.y};

    const float L = -LAMB_;
    const int base = y * NX_ + x;
    #pragma unroll
    for (int e = 0; e < 8; ++e)
        out[(8 * zo + e) * (NY_ * NX_) + base] = L * vals[e];
}

// ---------------------------------------------------------------------------
extern "C" void kernel_launch(void* const* d_in, const int* in_sizes, int n_in,
                              void* d_out, int out_size) {
    const float* x = (const float*)d_in[0];
    const float* p = (const float*)d_in[1];
    if (n_in >= 2 && in_sizes[0] == 786432) {   // defensive swap by size
        const float* tmp = x; x = p; p = tmp;
    }
    float* out = (float*)d_out;

    // Two no-ops keep the ncu capture point (-s 5) on fwd_kernel.
    noop_kernel<<<1, 32>>>();
    noop_kernel<<<1, 32>>>();
    pack_kernel<<<dim3(NX_ / 32, NY_), 256>>>(x);
    fwd_kernel<<<dim3(DET0_ / 32, A_, 2), 128>>>(p);
    bwd_kernel<<<dim3(NX_ / 16, NY_ / 4), 256>>>(out);
}